// round 6
// baseline (speedup 1.0000x reference)
#include <cuda_runtime.h>
#include <cuda_fp16.h>
#include <cstdint>
#include <cstddef>

// ---------------- problem constants ----------------
#define T_STEPS 512
#define BB      64
#define EE      512
#define HH      1024
#define DD      1536
#define NG      4096      // 4*H gate columns (order: f, i, c, o)
#define NCLS    10

// ---------------- recurrent kernel config ----------------
#define GBLK 128          // persistent grid (<= #SMs, co-resident)
#define JPB  8            // hidden units per block -> 32 gate-cols
#define RSTR 264          // smem h row stride in halves (512B + 16B pad)
#define CHALVES (64 * RSTR)   // halves per chunk buffer (16896)
#define CBYTES  (CHALVES * 2) // 33792

// ---------------- x-GEMM config (fp16) ----------------
#define XBM 128
#define XBN 128
#define XBK 32
#define XSTR 40           // smem row stride in halves (64B + 16B pad)
#define XKCH (EE / XBK)   // 16

// ---------------- prep sizing ----------------
#define WTOT ((size_t)4 * HH * (DD / 2))        // 3,145,728 weight half-pairs
#define WBLKN 12288                              // WTOT / 256
#define XTOT ((size_t)BB * T_STEPS * EE / 2)    // 8,388,608 x half-pairs
#define XBLKN 32768                              // XTOT / 256

// ---------------- device scratch (allocation-free) ----------------
__device__ float    d_Gx[(size_t)T_STEPS * BB * NG];   // x-side gate preacts (f,i,o pre-halved)
__device__ __half   d_X16[(size_t)BB * T_STEPS * EE];  // fp16 input
__device__ unsigned d_Wh16[(size_t)NG * HH / 2];       // recurrent weights, per-thread frag (half2)
__device__ __half   d_Wx16[(size_t)NG * EE];           // fp16 input weights [n][e] (f,i,o halved)
__device__ __half   d_hh[2][4 * 64 * 256];             // double-buffered hidden state [c][b][k]
__device__ float    d_hfin[BB * HH];                   // exact fp32 final h
__device__ unsigned d_barf[T_STEPS * 4 * 32];          // per-step per-quarter per-block flags

// ---------------- helpers ----------------
__device__ __forceinline__ void mma_fp16(float& c0, float& c1, float& c2, float& c3,
                                         unsigned a0, unsigned a1, unsigned a2, unsigned a3,
                                         unsigned b0, unsigned b1) {
    asm volatile(
        "mma.sync.aligned.m16n8k16.row.col.f32.f16.f16.f32 "
        "{%0,%1,%2,%3},{%4,%5,%6,%7},{%8,%9},{%0,%1,%2,%3};"
        : "+f"(c0), "+f"(c1), "+f"(c2), "+f"(c3)
        : "r"(a0), "r"(a1), "r"(a2), "r"(a3), "r"(b0), "r"(b1));
}

__device__ __forceinline__ uint32_t saddr(const void* p) {
    return (uint32_t)__cvta_generic_to_shared(p);
}
__device__ __forceinline__ void cpasync16(uint32_t dst, const void* src) {
    asm volatile("cp.async.cg.shared.global [%0], [%1], 16;" :: "r"(dst), "l"(src));
}
#define CP_COMMIT() asm volatile("cp.async.commit_group;")
#define CP_WAIT(N)  asm volatile("cp.async.wait_group %0;" :: "n"(N))

__device__ __forceinline__ void mbar_wait(uint32_t mbar, unsigned phase) {
    asm volatile(
        "{\n\t"
        ".reg .pred P;\n\t"
        "LW%=:\n\t"
        "mbarrier.try_wait.parity.acquire.cta.shared::cta.b64 P, [%0], %1, 0x989680;\n\t"
        "@P bra LD%=;\n\t"
        "bra LW%=;\n\t"
        "LD%=:\n\t"
        "}"
        :: "r"(mbar), "r"(phase) : "memory");
}

__device__ __forceinline__ float tanh_fast(float x) {
    float r;
    asm("tanh.approx.f32 %0, %1;" : "=f"(r) : "f"(x));
    return r;
}
__device__ __forceinline__ unsigned h2tanh(unsigned x) {
    unsigned r;
    asm("tanh.approx.f16x2 %0, %1;" : "=r"(r) : "r"(x));
    return r;
}
__device__ __forceinline__ float2 sig_pair_from_halved(float ax, float ay) {
    // input: x/2 (pre-halved preact); returns sigmoid(x) pair via f16x2 tanh
    __half2 h = __floats2half2_rn(ax, ay);
    unsigned u = *reinterpret_cast<unsigned*>(&h);
    u = h2tanh(u);
    __half2 t = *reinterpret_cast<__half2*>(&u);
    float2 tf = __half22float2(t);
    return make_float2(0.5f + 0.5f * tf.x, 0.5f + 0.5f * tf.y);
}

// ---------------- init ----------------
__global__ void k_init() {
    int i = blockIdx.x * blockDim.x + threadIdx.x;
    for (int j = i; j < T_STEPS * 4 * 32; j += gridDim.x * blockDim.x) d_barf[j] = 0u;
    unsigned* h = (unsigned*)&d_hh[0][0];
    for (int j = i; j < 2 * 4 * 64 * 256 / 2; j += gridDim.x * blockDim.x) h[j] = 0u;
}

// ---------------- merged prep: weights (split+scale+fp16) and x (fp16) ----------------
// f,i,o weights are pre-scaled by 0.5 so sigmoid(x) = 0.5 + 0.5*tanh(halved preact).
__global__ void k_prep(const float* __restrict__ Wf, const float* __restrict__ Wi,
                       const float* __restrict__ Wc, const float* __restrict__ Wo,
                       const float* __restrict__ X) {
    if (blockIdx.x < WBLKN) {
        size_t idx = (size_t)blockIdx.x * 256 + threadIdx.x;
        int d2  = (int)(idx % (DD / 2));
        int rem = (int)(idx / (DD / 2));
        int j   = rem % HH;
        int g   = rem / HH;
        int d   = 2 * d2;
        const float* W = (g == 0) ? Wf : (g == 1) ? Wi : (g == 2) ? Wc : Wo;
        float sc = (g == 2) ? 1.0f : 0.5f;
        float v0 = W[(size_t)j * DD + d] * sc;
        float v1 = W[(size_t)j * DD + d + 1] * sc;
        __half h0 = __float2half_rn(v0), h1 = __float2half_rn(v1);
        if (d < EE) {
            int n = g * HH + j;
            *(__half2*)(d_Wx16 + (size_t)n * EE + d) = __halves2half2(h0, h1);
        } else {
            int k = d - EE;                 // even
            int bid = j >> 3, jj = j & 7;
            int cstart = bid >> 5;
            int cc = ((k >> 8) - cstart) & 3;
            int k256 = k & 255;
            int sk = k256 >> 6;
            int s  = (k256 >> 4) & 3;
            int kk = k256 & 15;
            int breg = kk >> 3;
            int tg = (kk & 7) >> 1;
            int nh = g >> 1, ntl = g & 1;
            int w = nh * 4 + sk;
            int lane = (jj << 2) | tg;
            int u = cc * 16 + s * 4 + ntl * 2 + breg;
            unsigned pk = ((unsigned)__half_as_ushort(h1) << 16) |
                          (unsigned)__half_as_ushort(h0);   // lo = smaller k
            d_Wh16[(((size_t)bid * 8 + w) * 32 + lane) * 64 + u] = pk;
        }
    } else {
        size_t idx = (size_t)(blockIdx.x - WBLKN) * 256 + threadIdx.x;
        float2 v = ((const float2*)X)[idx];
        ((__half2*)d_X16)[idx] = __halves2half2(__float2half_rn(v.x), __float2half_rn(v.y));
    }
}

// ---------------- x-side GEMM (fp16): Gx[t][b][n] = X @ Wx^T + bias ----------------
__global__ void __launch_bounds__(256) k_gx_gemm(const float* __restrict__ bf, const float* __restrict__ bi,
                                                 const float* __restrict__ bc, const float* __restrict__ bo) {
    __shared__ __half As[2][XBM][XSTR];
    __shared__ __half Bs[2][XBN][XSTR];

    const int tid = threadIdx.x;
    const int warp = tid >> 5, lane = tid & 31;
    const int g8 = lane >> 2, tg = lane & 3;
    const int m0 = blockIdx.y * XBM;
    const int n0 = blockIdx.x * XBN;
    const int wm = (warp & 3) * 32;
    const int wn = (warp >> 2) * 64;

    float acc[2][8][4];
#pragma unroll
    for (int a = 0; a < 2; a++)
#pragma unroll
        for (int b = 0; b < 8; b++)
#pragma unroll
            for (int c = 0; c < 4; c++) acc[a][b][c] = 0.f;

    auto load_chunk = [&](int c, int buf) {
        int k0 = c * XBK;
#pragma unroll
        for (int i = 0; i < 2; i++) {
            int q = tid + i * 256;
            int row = q >> 2, kq = q & 3;
            cpasync16(saddr(&As[buf][row][kq * 8]),
                      d_X16 + (size_t)(m0 + row) * EE + k0 + kq * 8);
            cpasync16(saddr(&Bs[buf][row][kq * 8]),
                      d_Wx16 + (size_t)(n0 + row) * EE + k0 + kq * 8);
        }
    };

    load_chunk(0, 0);
    CP_COMMIT();

    for (int c = 0; c < XKCH; c++) {
        if (c + 1 < XKCH) {
            load_chunk(c + 1, (c + 1) & 1);
            CP_COMMIT();
            CP_WAIT(1);
        } else {
            CP_WAIT(0);
        }
        __syncthreads();
        const int buf = c & 1;
#pragma unroll
        for (int kk = 0; kk < XBK; kk += 16) {
            unsigned a[2][4];
#pragma unroll
            for (int mi = 0; mi < 2; mi++) {
                a[mi][0] = *(const unsigned*)&As[buf][wm + mi * 16 + g8][kk + 2 * tg];
                a[mi][1] = *(const unsigned*)&As[buf][wm + mi * 16 + 8 + g8][kk + 2 * tg];
                a[mi][2] = *(const unsigned*)&As[buf][wm + mi * 16 + g8][kk + 8 + 2 * tg];
                a[mi][3] = *(const unsigned*)&As[buf][wm + mi * 16 + 8 + g8][kk + 8 + 2 * tg];
            }
#pragma unroll
            for (int ni = 0; ni < 8; ni++) {
                unsigned b0 = *(const unsigned*)&Bs[buf][wn + ni * 8 + g8][kk + 2 * tg];
                unsigned b1 = *(const unsigned*)&Bs[buf][wn + ni * 8 + g8][kk + 8 + 2 * tg];
                mma_fp16(acc[0][ni][0], acc[0][ni][1], acc[0][ni][2], acc[0][ni][3],
                         a[0][0], a[0][1], a[0][2], a[0][3], b0, b1);
                mma_fp16(acc[1][ni][0], acc[1][ni][1], acc[1][ni][2], acc[1][ni][3],
                         a[1][0], a[1][1], a[1][2], a[1][3], b0, b1);
            }
        }
        __syncthreads();
    }

#pragma unroll
    for (int mi = 0; mi < 2; mi++) {
        int r0 = m0 + wm + mi * 16 + g8;
        int r1 = r0 + 8;
        size_t o0 = ((size_t)(r0 & (T_STEPS - 1)) * BB + (r0 >> 9)) * NG;
        size_t o1 = ((size_t)(r1 & (T_STEPS - 1)) * BB + (r1 >> 9)) * NG;
#pragma unroll
        for (int ni = 0; ni < 8; ni++) {
            int col = n0 + wn + ni * 8 + 2 * tg;
            int g = col >> 10;
            int jj = col & (HH - 1);
            const float* bp = (g == 0) ? bf : (g == 1) ? bi : (g == 2) ? bc : bo;
            float bsc = (g == 2) ? 1.0f : 0.5f;     // match weight pre-scaling
            float bv0 = bp[jj] * bsc, bv1 = bp[jj + 1] * bsc;
            float2 v0 = make_float2(acc[mi][ni][0] + bv0, acc[mi][ni][1] + bv1);
            float2 v1 = make_float2(acc[mi][ni][2] + bv0, acc[mi][ni][3] + bv1);
            *(float2*)(d_Gx + o0 + col) = v0;
            *(float2*)(d_Gx + o1 + col) = v1;
        }
    }
}

// ---------------- persistent recurrent kernel (warp-specialized) ----------------
__global__ void __launch_bounds__(288, 1) k_lstm_rec() {
    extern __shared__ char smemc[];
    __half*   hs   = (__half*)smemc;                             // [4][64][RSTR]
    float*    Csm  = (float*)(smemc + 4 * CBYTES);               // [4 sk][64 m][34]
    uint64_t* mbar = (uint64_t*)(smemc + 4 * CBYTES + 4 * 64 * 34 * 4);

    const int tid  = threadIdx.x;
    const int bid  = blockIdx.x;
    const int w    = tid >> 5, lane = tid & 31;
    const int g8   = lane >> 2, tg = lane & 3;
    const int j0   = bid * JPB;
    const int cstart = bid >> 5;

    uint32_t full_mb[4], empty_mb[4];
#pragma unroll
    for (int i = 0; i < 4; i++) {
        full_mb[i]  = saddr(&mbar[i]);
        empty_mb[i] = saddr(&mbar[4 + i]);
    }

    if (tid == 0) {
#pragma unroll
        for (int i = 0; i < 4; i++) {
            asm volatile("mbarrier.init.shared::cta.b64 [%0], 1;" :: "r"(full_mb[i]));
            asm volatile("mbarrier.init.shared::cta.b64 [%0], 8;" :: "r"(empty_mb[i]));
        }
        asm volatile("fence.proxy.async.shared::cta;" ::: "memory");
    }
    __syncthreads();

    if (w == 8) {
        // ---------------- producer warp ----------------
        for (int t = 0; t < T_STEPS; t++) {
            const __half* hsrc = &d_hh[t & 1][0];
#pragma unroll 1
            for (int cc = 0; cc < 4; cc++) {
                int ca = (cc + cstart) & 3;
                if (t > 0) {
                    mbar_wait(empty_mb[cc], (t - 1) & 1);
                    const unsigned* fp = d_barf + ((size_t)(t - 1) * 4 + ca) * 32 + lane;
                    unsigned v;
                    do {
                        asm volatile("ld.acquire.gpu.global.u32 %0, [%1];"
                                     : "=r"(v) : "l"(fp) : "memory");
                    } while (__ballot_sync(0xFFFFFFFFu, v != 0u) != 0xFFFFFFFFu);
                    asm volatile("fence.proxy.async;" ::: "memory");
                }
                if (lane == 0)
                    asm volatile("mbarrier.arrive.expect_tx.shared::cta.b64 _, [%0], %1;"
                                 :: "r"(full_mb[cc]), "r"(32768) : "memory");
                __syncwarp();
#pragma unroll
                for (int rr = 0; rr < 2; rr++) {
                    int r = lane + rr * 32;
                    uint32_t dst = saddr(hs) + cc * CBYTES + r * (RSTR * 2);
                    const __half* src = hsrc + ca * 16384 + r * 256;
                    asm volatile(
                        "cp.async.bulk.shared::cta.global.mbarrier::complete_tx::bytes [%0], [%1], %2, [%3];"
                        :: "r"(dst), "l"(src), "r"(512), "r"(full_mb[cc]) : "memory");
                }
            }
        }
        return;
    }

    // ---------------- compute warps (0-7) ----------------
    const int nh = w >> 2, sk = w & 3;

    unsigned wreg[64];
    {
        const uint4* wp = (const uint4*)(d_Wh16 + (((size_t)bid * 8 + w) * 32 + lane) * 64);
#pragma unroll
        for (int i = 0; i < 16; i++) *(uint4*)&wreg[i * 4] = wp[i];
    }

    const int eb  = tid >> 2;
    const int ej2 = tid & 3;
    float2 cst = make_float2(0.f, 0.f);

    for (int t = 0; t < T_STEPS; t++) {
        const float* gx = d_Gx + (size_t)t * BB * NG + (size_t)eb * NG + j0 + 2 * ej2;
        float2 gxv[4];
#pragma unroll
        for (int g = 0; g < 4; g++) gxv[g] = __ldg((const float2*)(gx + g * HH));

        float acc[2][4][4];
#pragma unroll
        for (int a = 0; a < 2; a++)
#pragma unroll
            for (int b = 0; b < 4; b++)
#pragma unroll
                for (int c = 0; c < 4; c++) acc[a][b][c] = 0.f;

#pragma unroll 1
        for (int cc = 0; cc < 4; cc++) {
            mbar_wait(full_mb[cc], t & 1);
            const __half* hb = hs + cc * CHALVES + sk * 64;
#pragma unroll
            for (int s = 0; s < 4; s++) {
                const int col = s * 16 + 2 * tg;
#pragma unroll
                for (int mt = 0; mt < 4; mt++) {
                    const __half* rp = hb + (mt * 16 + g8) * RSTR + col;
                    unsigned a0 = *(const unsigned*)rp;
                    unsigned a1 = *(const unsigned*)(rp + 8 * RSTR);
                    unsigned a2 = *(const unsigned*)(rp + 8);
                    unsigned a3 = *(const unsigned*)(rp + 8 * RSTR + 8);
#pragma unroll
                    for (int ntl = 0; ntl < 2; ntl++) {
                        const int u = cc * 16 + s * 4 + ntl * 2;
                        mma_fp16(acc[ntl][mt][0], acc[ntl][mt][1], acc[ntl][mt][2], acc[ntl][mt][3],
                                 a0, a1, a2, a3, wreg[u], wreg[u + 1]);
                    }
                }
            }
            __syncwarp();
            if (lane == 0)
                asm volatile("mbarrier.arrive.shared::cta.b64 _, [%0];"
                             :: "r"(empty_mb[cc]) : "memory");
        }

        // stage partials: Csm[sk][m][n(32) padded to 34]
#pragma unroll
        for (int ntl = 0; ntl < 2; ntl++) {
            const int nb = nh * 16 + ntl * 8 + 2 * tg;
#pragma unroll
            for (int mt = 0; mt < 4; mt++) {
                float* cp = Csm + (size_t)(sk * 64 + mt * 16 + g8) * 34 + nb;
                *(float2*)cp              = make_float2(acc[ntl][mt][0], acc[ntl][mt][1]);
                *(float2*)(cp + 8 * 34)   = make_float2(acc[ntl][mt][2], acc[ntl][mt][3]);
            }
        }
        asm volatile("bar.sync 1, 256;" ::: "memory");

        // epilogue: reduce 4 k-slices, gates (f16x2 sigmoids, fp32 tanh), update c, write h
        {
            float2 a4[4];
#pragma unroll
            for (int g = 0; g < 4; g++) {
                float2 s = gxv[g];
#pragma unroll
                for (int q = 0; q < 4; q++) {
                    float2 v = *(const float2*)(Csm + (size_t)(q * 64 + eb) * 34 + g * 8 + 2 * ej2);
                    s.x += v.x; s.y += v.y;
                }
                a4[g] = s;
            }
            // a4[0],a4[1],a4[3] are pre-halved preacts (weights scaled 0.5)
            float2 fg = sig_pair_from_halved(a4[0].x, a4[0].y);
            float2 ig = sig_pair_from_halved(a4[1].x, a4[1].y);
            float2 og = sig_pair_from_halved(a4[3].x, a4[3].y);
            float cgx = tanh_fast(a4[2].x), cgy = tanh_fast(a4[2].y);
            cst.x = __fmaf_rn(fg.x, cst.x, ig.x * cgx);
            cst.y = __fmaf_rn(fg.y, cst.y, ig.y * cgy);
            float hnx = og.x * tanh_fast(cst.x);
            float hny = og.y * tanh_fast(cst.y);
            __half2* hd = (__half2*)(&d_hh[(t + 1) & 1][0] +
                                     cstart * 16384 + eb * 256 + (j0 & 255) + 2 * ej2);
            *hd = __halves2half2(__float2half_rn(hnx), __float2half_rn(hny));
            if (t == T_STEPS - 1)
                *(float2*)(d_hfin + (size_t)eb * HH + j0 + 2 * ej2) = make_float2(hnx, hny);
        }

        asm volatile("bar.sync 1, 256;" ::: "memory");
        if (tid == 0 && t < T_STEPS - 1) {
            const unsigned* fp = d_barf + ((size_t)t * 4 + cstart) * 32 + (bid & 31);
            asm volatile("st.release.gpu.global.u32 [%0], %1;"
                         :: "l"(fp), "r"(1u) : "memory");
        }
    }
}

// ---------------- final FC (exact fp32) ----------------
__global__ void k_fc(const float* __restrict__ Wfc, const float* __restrict__ bfc,
                     float* __restrict__ out) {
    int b = blockIdx.x, n = blockIdx.y;
    const float* h = d_hfin + (size_t)b * HH;
    const float* w = Wfc + (size_t)n * HH;
    float s = 0.f;
    for (int k = threadIdx.x; k < HH; k += 128) s += h[k] * w[k];
#pragma unroll
    for (int o = 16; o > 0; o >>= 1) s += __shfl_down_sync(0xFFFFFFFFu, s, o);
    __shared__ float red[4];
    if ((threadIdx.x & 31) == 0) red[threadIdx.x >> 5] = s;
    __syncthreads();
    if (threadIdx.x == 0)
        out[b * NCLS + n] = red[0] + red[1] + red[2] + red[3] + bfc[n];
}

// ---------------- launch ----------------
extern "C" void kernel_launch(void* const* d_in, const int* in_sizes, int n_in,
                              void* d_out, int out_size) {
    const float* X   = (const float*)d_in[0];
    const float* Wf  = (const float*)d_in[1];
    const float* bf  = (const float*)d_in[2];
    const float* Wi  = (const float*)d_in[3];
    const float* bi  = (const float*)d_in[4];
    const float* Wc  = (const float*)d_in[5];
    const float* bc  = (const float*)d_in[6];
    const float* Wo  = (const float*)d_in[7];
    const float* bo  = (const float*)d_in[8];
    const float* Wfc = (const float*)d_in[9];
    const float* bfc = (const float*)d_in[10];

    const int rec_smem = 4 * CBYTES + 4 * 64 * 34 * 4 + 64;  // 135168 + 34816 + 64
    cudaFuncSetAttribute(k_lstm_rec, cudaFuncAttributeMaxDynamicSharedMemorySize, rec_smem);

    k_init<<<64, 256>>>();
    k_prep<<<WBLKN + XBLKN, 256>>>(Wf, Wi, Wc, Wo, X);
    k_gx_gemm<<<dim3(NG / XBN, (BB * T_STEPS) / XBM), 256>>>(bf, bi, bc, bo);
    k_lstm_rec<<<GBLK, 288, rec_smem>>>();
    k_fc<<<dim3(BB, NCLS), 128>>>(Wfc, bfc, (float*)d_out);
}

// round 7
// speedup vs baseline: 1.4343x; 1.4343x over previous
#include <cuda_runtime.h>
#include <cuda_fp16.h>
#include <cstdint>
#include <cstddef>

// ---------------- problem constants ----------------
#define T_STEPS 512
#define BB      64
#define EE      512
#define HH      1024
#define DD      1536
#define NG      4096      // 4*H gate columns (order: f, i, c, o)
#define NCLS    10

// ---------------- recurrent kernel config ----------------
#define GBLK 128          // persistent grid (<= #SMs, co-resident)
#define JPB  8            // hidden units per block -> 32 gate-cols
#define RSTR 264          // smem h row stride in halves (512B + 16B pad)
#define CHALVES (64 * RSTR)   // halves per chunk buffer (16896)
#define CBYTES  (CHALVES * 2) // 33792

// ---------------- x-GEMM config (fp16) ----------------
#define XBM 128
#define XBN 128
#define XBK 32
#define XSTR 40           // smem row stride in halves (64B + 16B pad)
#define XKCH (EE / XBK)   // 16

// ---------------- prep sizing ----------------
#define WTOT ((size_t)4 * HH * (DD / 2))        // 3,145,728 weight half-pairs
#define WBLKN 12288                              // WTOT / 256
#define XTOT ((size_t)BB * T_STEPS * EE / 2)    // 8,388,608 x half-pairs
#define XBLKN 32768                              // XTOT / 256

// ---------------- device scratch (allocation-free) ----------------
__device__ float    d_Gx[(size_t)T_STEPS * BB * NG];   // x-side gate preacts (f,i,o pre-halved)
__device__ __half   d_X16[(size_t)BB * T_STEPS * EE];  // fp16 input
__device__ unsigned d_Wh16[(size_t)NG * HH / 2];       // recurrent weights, per-thread frag (half2)
__device__ __half   d_Wx16[(size_t)NG * EE];           // fp16 input weights [n][e] (f,i,o halved)
__device__ __half   d_hh[2][4 * 64 * 256];             // double-buffered hidden state [c][b][k]
__device__ float    d_hfin[BB * HH];                   // exact fp32 final h
__device__ unsigned d_bar[T_STEPS];                    // per-step grid-barrier counters

// ---------------- helpers ----------------
__device__ __forceinline__ void mma_fp16(float& c0, float& c1, float& c2, float& c3,
                                         unsigned a0, unsigned a1, unsigned a2, unsigned a3,
                                         unsigned b0, unsigned b1) {
    asm volatile(
        "mma.sync.aligned.m16n8k16.row.col.f32.f16.f16.f32 "
        "{%0,%1,%2,%3},{%4,%5,%6,%7},{%8,%9},{%0,%1,%2,%3};"
        : "+f"(c0), "+f"(c1), "+f"(c2), "+f"(c3)
        : "r"(a0), "r"(a1), "r"(a2), "r"(a3), "r"(b0), "r"(b1));
}

__device__ __forceinline__ uint32_t saddr(const void* p) {
    return (uint32_t)__cvta_generic_to_shared(p);
}
__device__ __forceinline__ void cpasync16(uint32_t dst, const void* src) {
    asm volatile("cp.async.cg.shared.global [%0], [%1], 16;" :: "r"(dst), "l"(src));
}
#define CP_COMMIT() asm volatile("cp.async.commit_group;")
#define CP_WAIT(N)  asm volatile("cp.async.wait_group %0;" :: "n"(N))

__device__ __forceinline__ void mbar_wait(uint32_t mbar, unsigned phase) {
    asm volatile(
        "{\n\t"
        ".reg .pred P;\n\t"
        "LW%=:\n\t"
        "mbarrier.try_wait.parity.acquire.cta.shared::cta.b64 P, [%0], %1, 0x989680;\n\t"
        "@P bra LD%=;\n\t"
        "bra LW%=;\n\t"
        "LD%=:\n\t"
        "}"
        :: "r"(mbar), "r"(phase) : "memory");
}

__device__ __forceinline__ float tanh_fast(float x) {
    float r;
    asm("tanh.approx.f32 %0, %1;" : "=f"(r) : "f"(x));
    return r;
}
__device__ __forceinline__ unsigned h2tanh(unsigned x) {
    unsigned r;
    asm("tanh.approx.f16x2 %0, %1;" : "=r"(r) : "r"(x));
    return r;
}
__device__ __forceinline__ float2 sig_pair_from_halved(float ax, float ay) {
    // input: x/2 (pre-halved preact); returns sigmoid(x) pair via f16x2 tanh
    __half2 h = __floats2half2_rn(ax, ay);
    unsigned u = *reinterpret_cast<unsigned*>(&h);
    u = h2tanh(u);
    __half2 t = *reinterpret_cast<__half2*>(&u);
    float2 tf = __half22float2(t);
    return make_float2(0.5f + 0.5f * tf.x, 0.5f + 0.5f * tf.y);
}

// ---------------- init ----------------
__global__ void k_init() {
    int i = blockIdx.x * blockDim.x + threadIdx.x;
    if (i < T_STEPS) d_bar[i] = 0u;
    unsigned* h = (unsigned*)&d_hh[0][0];
    for (int j = i; j < 2 * 4 * 64 * 256 / 2; j += gridDim.x * blockDim.x) h[j] = 0u;
}

// ---------------- merged prep: weights (split+scale+fp16) and x (fp16) ----------------
// f,i,o weights are pre-scaled by 0.5 so sigmoid(x) = 0.5 + 0.5*tanh(halved preact).
__global__ void k_prep(const float* __restrict__ Wf, const float* __restrict__ Wi,
                       const float* __restrict__ Wc, const float* __restrict__ Wo,
                       const float* __restrict__ X) {
    if (blockIdx.x < WBLKN) {
        size_t idx = (size_t)blockIdx.x * 256 + threadIdx.x;
        int d2  = (int)(idx % (DD / 2));
        int rem = (int)(idx / (DD / 2));
        int j   = rem % HH;
        int g   = rem / HH;
        int d   = 2 * d2;
        const float* W = (g == 0) ? Wf : (g == 1) ? Wi : (g == 2) ? Wc : Wo;
        float sc = (g == 2) ? 1.0f : 0.5f;
        float v0 = W[(size_t)j * DD + d] * sc;
        float v1 = W[(size_t)j * DD + d + 1] * sc;
        __half h0 = __float2half_rn(v0), h1 = __float2half_rn(v1);
        if (d < EE) {
            int n = g * HH + j;
            *(__half2*)(d_Wx16 + (size_t)n * EE + d) = __halves2half2(h0, h1);
        } else {
            int k = d - EE;                 // even
            int bid = j >> 3, jj = j & 7;
            int cstart = bid >> 5;
            int cc = ((k >> 8) - cstart) & 3;
            int k256 = k & 255;
            int sk = k256 >> 6;
            int s  = (k256 >> 4) & 3;
            int kk = k256 & 15;
            int breg = kk >> 3;
            int tg = (kk & 7) >> 1;
            int nh = g >> 1, ntl = g & 1;
            int w = nh * 4 + sk;
            int lane = (jj << 2) | tg;
            int u = cc * 16 + s * 4 + ntl * 2 + breg;
            unsigned pk = ((unsigned)__half_as_ushort(h1) << 16) |
                          (unsigned)__half_as_ushort(h0);   // lo = smaller k
            d_Wh16[(((size_t)bid * 8 + w) * 32 + lane) * 64 + u] = pk;
        }
    } else {
        size_t idx = (size_t)(blockIdx.x - WBLKN) * 256 + threadIdx.x;
        float2 v = ((const float2*)X)[idx];
        ((__half2*)d_X16)[idx] = __halves2half2(__float2half_rn(v.x), __float2half_rn(v.y));
    }
}

// ---------------- x-side GEMM (fp16): Gx[t][b][n] = X @ Wx^T + bias ----------------
__global__ void __launch_bounds__(256) k_gx_gemm(const float* __restrict__ bf, const float* __restrict__ bi,
                                                 const float* __restrict__ bc, const float* __restrict__ bo) {
    __shared__ __half As[2][XBM][XSTR];
    __shared__ __half Bs[2][XBN][XSTR];

    const int tid = threadIdx.x;
    const int warp = tid >> 5, lane = tid & 31;
    const int g8 = lane >> 2, tg = lane & 3;
    const int m0 = blockIdx.y * XBM;
    const int n0 = blockIdx.x * XBN;
    const int wm = (warp & 3) * 32;
    const int wn = (warp >> 2) * 64;

    float acc[2][8][4];
#pragma unroll
    for (int a = 0; a < 2; a++)
#pragma unroll
        for (int b = 0; b < 8; b++)
#pragma unroll
            for (int c = 0; c < 4; c++) acc[a][b][c] = 0.f;

    auto load_chunk = [&](int c, int buf) {
        int k0 = c * XBK;
#pragma unroll
        for (int i = 0; i < 2; i++) {
            int q = tid + i * 256;
            int row = q >> 2, kq = q & 3;
            cpasync16(saddr(&As[buf][row][kq * 8]),
                      d_X16 + (size_t)(m0 + row) * EE + k0 + kq * 8);
            cpasync16(saddr(&Bs[buf][row][kq * 8]),
                      d_Wx16 + (size_t)(n0 + row) * EE + k0 + kq * 8);
        }
    };

    load_chunk(0, 0);
    CP_COMMIT();

    for (int c = 0; c < XKCH; c++) {
        if (c + 1 < XKCH) {
            load_chunk(c + 1, (c + 1) & 1);
            CP_COMMIT();
            CP_WAIT(1);
        } else {
            CP_WAIT(0);
        }
        __syncthreads();
        const int buf = c & 1;
#pragma unroll
        for (int kk = 0; kk < XBK; kk += 16) {
            unsigned a[2][4];
#pragma unroll
            for (int mi = 0; mi < 2; mi++) {
                a[mi][0] = *(const unsigned*)&As[buf][wm + mi * 16 + g8][kk + 2 * tg];
                a[mi][1] = *(const unsigned*)&As[buf][wm + mi * 16 + 8 + g8][kk + 2 * tg];
                a[mi][2] = *(const unsigned*)&As[buf][wm + mi * 16 + g8][kk + 8 + 2 * tg];
                a[mi][3] = *(const unsigned*)&As[buf][wm + mi * 16 + 8 + g8][kk + 8 + 2 * tg];
            }
#pragma unroll
            for (int ni = 0; ni < 8; ni++) {
                unsigned b0 = *(const unsigned*)&Bs[buf][wn + ni * 8 + g8][kk + 2 * tg];
                unsigned b1 = *(const unsigned*)&Bs[buf][wn + ni * 8 + g8][kk + 8 + 2 * tg];
                mma_fp16(acc[0][ni][0], acc[0][ni][1], acc[0][ni][2], acc[0][ni][3],
                         a[0][0], a[0][1], a[0][2], a[0][3], b0, b1);
                mma_fp16(acc[1][ni][0], acc[1][ni][1], acc[1][ni][2], acc[1][ni][3],
                         a[1][0], a[1][1], a[1][2], a[1][3], b0, b1);
            }
        }
        __syncthreads();
    }

#pragma unroll
    for (int mi = 0; mi < 2; mi++) {
        int r0 = m0 + wm + mi * 16 + g8;
        int r1 = r0 + 8;
        size_t o0 = ((size_t)(r0 & (T_STEPS - 1)) * BB + (r0 >> 9)) * NG;
        size_t o1 = ((size_t)(r1 & (T_STEPS - 1)) * BB + (r1 >> 9)) * NG;
#pragma unroll
        for (int ni = 0; ni < 8; ni++) {
            int col = n0 + wn + ni * 8 + 2 * tg;
            int g = col >> 10;
            int jj = col & (HH - 1);
            const float* bp = (g == 0) ? bf : (g == 1) ? bi : (g == 2) ? bc : bo;
            float bsc = (g == 2) ? 1.0f : 0.5f;     // match weight pre-scaling
            float bv0 = bp[jj] * bsc, bv1 = bp[jj + 1] * bsc;
            float2 v0 = make_float2(acc[mi][ni][0] + bv0, acc[mi][ni][1] + bv1);
            float2 v1 = make_float2(acc[mi][ni][2] + bv0, acc[mi][ni][3] + bv1);
            *(float2*)(d_Gx + o0 + col) = v0;
            *(float2*)(d_Gx + o1 + col) = v1;
        }
    }
}

// ---------------- persistent recurrent kernel (warp-specialized) ----------------
// 128 blocks x 288 threads. Warps 0-7 compute, warp 8 produces.
// One grid barrier per step (red.release + 1-lane acquire poll w/ backoff).
__global__ void __launch_bounds__(288, 1) k_lstm_rec() {
    extern __shared__ char smemc[];
    __half*   hs   = (__half*)smemc;                             // [4][64][RSTR]
    float*    Csm  = (float*)(smemc + 4 * CBYTES);               // [4 sk][64 m][34]
    uint64_t* mbar = (uint64_t*)(smemc + 4 * CBYTES + 4 * 64 * 34 * 4);

    const int tid  = threadIdx.x;
    const int bid  = blockIdx.x;
    const int w    = tid >> 5, lane = tid & 31;
    const int g8   = lane >> 2, tg = lane & 3;
    const int j0   = bid * JPB;
    const int cstart = bid >> 5;

    uint32_t full_mb[4];
#pragma unroll
    for (int i = 0; i < 4; i++) full_mb[i] = saddr(&mbar[i]);

    if (tid == 0) {
#pragma unroll
        for (int i = 0; i < 4; i++)
            asm volatile("mbarrier.init.shared::cta.b64 [%0], 1;" :: "r"(full_mb[i]));
        asm volatile("fence.proxy.async.shared::cta;" ::: "memory");
    }
    __syncthreads();

    if (w == 8) {
        // ---------------- producer warp ----------------
        for (int t = 0; t < T_STEPS; t++) {
            const __half* hsrc = &d_hh[t & 1][0];
            if (t > 0) {
                if (lane == 0) {
                    const unsigned* p = &d_bar[t - 1];
                    unsigned v;
                    while (true) {
                        asm volatile("ld.acquire.gpu.global.u32 %0, [%1];"
                                     : "=r"(v) : "l"(p) : "memory");
                        if (v >= (unsigned)GBLK) break;
                        __nanosleep(64);
                    }
                }
                __syncwarp();
                asm volatile("fence.proxy.async;" ::: "memory");
            }
#pragma unroll
            for (int cc = 0; cc < 4; cc++) {
                int ca = (cc + cstart) & 3;
                if (lane == 0)
                    asm volatile("mbarrier.arrive.expect_tx.shared::cta.b64 _, [%0], %1;"
                                 :: "r"(full_mb[cc]), "r"(32768) : "memory");
                __syncwarp();
#pragma unroll
                for (int rr = 0; rr < 2; rr++) {
                    int r = lane + rr * 32;
                    uint32_t dst = saddr(hs) + cc * CBYTES + r * (RSTR * 2);
                    const __half* src = hsrc + ca * 16384 + r * 256;
                    asm volatile(
                        "cp.async.bulk.shared::cta.global.mbarrier::complete_tx::bytes [%0], [%1], %2, [%3];"
                        :: "r"(dst), "l"(src), "r"(512), "r"(full_mb[cc]) : "memory");
                }
            }
        }
        return;
    }

    // ---------------- compute warps (0-7) ----------------
    const int nh = w >> 2, sk = w & 3;

    unsigned wreg[64];
    {
        const uint4* wp = (const uint4*)(d_Wh16 + (((size_t)bid * 8 + w) * 32 + lane) * 64);
#pragma unroll
        for (int i = 0; i < 16; i++) *(uint4*)&wreg[i * 4] = wp[i];
    }

    const int eb  = tid >> 2;
    const int ej2 = tid & 3;
    float2 cst = make_float2(0.f, 0.f);

    for (int t = 0; t < T_STEPS; t++) {
        const float* gx = d_Gx + (size_t)t * BB * NG + (size_t)eb * NG + j0 + 2 * ej2;
        float2 gxv[4];
#pragma unroll
        for (int g = 0; g < 4; g++) gxv[g] = __ldg((const float2*)(gx + g * HH));

        float acc[2][4][4];
#pragma unroll
        for (int a = 0; a < 2; a++)
#pragma unroll
            for (int b = 0; b < 4; b++)
#pragma unroll
                for (int c = 0; c < 4; c++) acc[a][b][c] = 0.f;

#pragma unroll 1
        for (int cc = 0; cc < 4; cc++) {
            mbar_wait(full_mb[cc], t & 1);
            const __half* hb = hs + cc * CHALVES + sk * 64;
#pragma unroll
            for (int s = 0; s < 4; s++) {
                const int col = s * 16 + 2 * tg;
#pragma unroll
                for (int mt = 0; mt < 4; mt++) {
                    const __half* rp = hb + (mt * 16 + g8) * RSTR + col;
                    unsigned a0 = *(const unsigned*)rp;
                    unsigned a1 = *(const unsigned*)(rp + 8 * RSTR);
                    unsigned a2 = *(const unsigned*)(rp + 8);
                    unsigned a3 = *(const unsigned*)(rp + 8 * RSTR + 8);
#pragma unroll
                    for (int ntl = 0; ntl < 2; ntl++) {
                        const int u = cc * 16 + s * 4 + ntl * 2;
                        mma_fp16(acc[ntl][mt][0], acc[ntl][mt][1], acc[ntl][mt][2], acc[ntl][mt][3],
                                 a0, a1, a2, a3, wreg[u], wreg[u + 1]);
                    }
                }
            }
        }

        // stage partials: Csm[sk][m][n(32) padded to 34]
#pragma unroll
        for (int ntl = 0; ntl < 2; ntl++) {
            const int nb = nh * 16 + ntl * 8 + 2 * tg;
#pragma unroll
            for (int mt = 0; mt < 4; mt++) {
                float* cp = Csm + (size_t)(sk * 64 + mt * 16 + g8) * 34 + nb;
                *(float2*)cp              = make_float2(acc[ntl][mt][0], acc[ntl][mt][1]);
                *(float2*)(cp + 8 * 34)   = make_float2(acc[ntl][mt][2], acc[ntl][mt][3]);
            }
        }
        asm volatile("bar.sync 1, 256;" ::: "memory");

        // epilogue: reduce 4 k-slices, gates (f16x2 sigmoids, fp32 tanh), update c, write h
        {
            float2 a4[4];
#pragma unroll
            for (int g = 0; g < 4; g++) {
                float2 s = gxv[g];
#pragma unroll
                for (int q = 0; q < 4; q++) {
                    float2 v = *(const float2*)(Csm + (size_t)(q * 64 + eb) * 34 + g * 8 + 2 * ej2);
                    s.x += v.x; s.y += v.y;
                }
                a4[g] = s;
            }
            // a4[0],a4[1],a4[3] are pre-halved preacts (weights scaled 0.5)
            float2 fg = sig_pair_from_halved(a4[0].x, a4[0].y);
            float2 ig = sig_pair_from_halved(a4[1].x, a4[1].y);
            float2 og = sig_pair_from_halved(a4[3].x, a4[3].y);
            float cgx = tanh_fast(a4[2].x), cgy = tanh_fast(a4[2].y);
            cst.x = __fmaf_rn(fg.x, cst.x, ig.x * cgx);
            cst.y = __fmaf_rn(fg.y, cst.y, ig.y * cgy);
            float hnx = og.x * tanh_fast(cst.x);
            float hny = og.y * tanh_fast(cst.y);
            __half2* hd = (__half2*)(&d_hh[(t + 1) & 1][0] +
                                     cstart * 16384 + eb * 256 + (j0 & 255) + 2 * ej2);
            *hd = __halves2half2(__float2half_rn(hnx), __float2half_rn(hny));
            if (t == T_STEPS - 1)
                *(float2*)(d_hfin + (size_t)eb * HH + j0 + 2 * ej2) = make_float2(hnx, hny);
        }

        asm volatile("bar.sync 1, 256;" ::: "memory");
        if (tid == 0 && t < T_STEPS - 1)
            asm volatile("red.release.gpu.global.add.u32 [%0], %1;"
                         :: "l"(&d_bar[t]), "r"(1u) : "memory");
    }
}

// ---------------- final FC (exact fp32) ----------------
__global__ void k_fc(const float* __restrict__ Wfc, const float* __restrict__ bfc,
                     float* __restrict__ out) {
    int b = blockIdx.x, n = blockIdx.y;
    const float* h = d_hfin + (size_t)b * HH;
    const float* w = Wfc + (size_t)n * HH;
    float s = 0.f;
    for (int k = threadIdx.x; k < HH; k += 128) s += h[k] * w[k];
#pragma unroll
    for (int o = 16; o > 0; o >>= 1) s += __shfl_down_sync(0xFFFFFFFFu, s, o);
    __shared__ float red[4];
    if ((threadIdx.x & 31) == 0) red[threadIdx.x >> 5] = s;
    __syncthreads();
    if (threadIdx.x == 0)
        out[b * NCLS + n] = red[0] + red[1] + red[2] + red[3] + bfc[n];
}

// ---------------- launch ----------------
extern "C" void kernel_launch(void* const* d_in, const int* in_sizes, int n_in,
                              void* d_out, int out_size) {
    const float* X   = (const float*)d_in[0];
    const float* Wf  = (const float*)d_in[1];
    const float* bf  = (const float*)d_in[2];
    const float* Wi  = (const float*)d_in[3];
    const float* bi  = (const float*)d_in[4];
    const float* Wc  = (const float*)d_in[5];
    const float* bc  = (const float*)d_in[6];
    const float* Wo  = (const float*)d_in[7];
    const float* bo  = (const float*)d_in[8];
    const float* Wfc = (const float*)d_in[9];
    const float* bfc = (const float*)d_in[10];

    const int rec_smem = 4 * CBYTES + 4 * 64 * 34 * 4 + 64;  // 135168 + 34816 + 64
    cudaFuncSetAttribute(k_lstm_rec, cudaFuncAttributeMaxDynamicSharedMemorySize, rec_smem);

    k_init<<<64, 256>>>();
    k_prep<<<WBLKN + XBLKN, 256>>>(Wf, Wi, Wc, Wo, X);
    k_gx_gemm<<<dim3(NG / XBN, (BB * T_STEPS) / XBM), 256>>>(bf, bi, bc, bo);
    k_lstm_rec<<<GBLK, 288, rec_smem>>>();
    k_fc<<<dim3(BB, NCLS), 128>>>(Wfc, bfc, (float*)d_out);
}

// round 8
// speedup vs baseline: 2.7057x; 1.8863x over previous
#include <cuda_runtime.h>
#include <cuda_fp16.h>
#include <cstdint>
#include <cstddef>

// ---------------- problem constants ----------------
#define T_STEPS 512
#define BB      64
#define EE      512
#define HH      1024
#define DD      1536
#define NG      4096      // 4*H gate columns (order: f, i, c, o)
#define NCLS    10

// ---------------- recurrent kernel config ----------------
#define GBLK 128          // persistent grid (<= #SMs, co-resident)
#define JPB  8            // hidden units per block -> 32 gate-cols
#define CHALVES 16384     // halves per chunk (64 rows x 256)
#define CBYTES  32768     // bytes per chunk

// ---------------- x-GEMM config (fp16) ----------------
#define XBM 128
#define XBN 128
#define XBK 32
#define XSTR 40           // smem row stride in halves (64B + 16B pad)
#define XKCH (EE / XBK)   // 16

// ---------------- prep sizing ----------------
#define WTOT ((size_t)4 * HH * (DD / 2))        // 3,145,728 weight half-pairs
#define WBLKN 12288                              // WTOT / 256
#define XTOT ((size_t)BB * T_STEPS * EE / 2)    // 8,388,608 x half-pairs
#define XBLKN 32768                              // XTOT / 256

// ---------------- device scratch (allocation-free) ----------------
__device__ float    d_Gx[(size_t)T_STEPS * BB * NG];   // x-side gate preacts (f,i,o pre-halved)
__device__ __half   d_X16[(size_t)BB * T_STEPS * EE];  // fp16 input
__device__ unsigned d_Wh16[(size_t)NG * HH / 2];       // recurrent weights, per-thread frag (half2)
__device__ __half   d_Wx16[(size_t)NG * EE];           // fp16 input weights [n][e] (f,i,o halved)
__device__ __align__(128) __half d_hh[2][4 * CHALVES]; // double-buffered h, chunk-major, XOR-swizzled rows
__device__ float    d_hfin[BB * HH];                   // exact fp32 final h
__device__ unsigned d_bar[T_STEPS];                    // per-step grid-barrier counters

// ---------------- helpers ----------------
__device__ __forceinline__ void mma_fp16(float& c0, float& c1, float& c2, float& c3,
                                         unsigned a0, unsigned a1, unsigned a2, unsigned a3,
                                         unsigned b0, unsigned b1) {
    asm volatile(
        "mma.sync.aligned.m16n8k16.row.col.f32.f16.f16.f32 "
        "{%0,%1,%2,%3},{%4,%5,%6,%7},{%8,%9},{%0,%1,%2,%3};"
        : "+f"(c0), "+f"(c1), "+f"(c2), "+f"(c3)
        : "r"(a0), "r"(a1), "r"(a2), "r"(a3), "r"(b0), "r"(b1));
}

__device__ __forceinline__ uint32_t saddr(const void* p) {
    return (uint32_t)__cvta_generic_to_shared(p);
}
__device__ __forceinline__ void cpasync16(uint32_t dst, const void* src) {
    asm volatile("cp.async.cg.shared.global [%0], [%1], 16;" :: "r"(dst), "l"(src));
}
#define CP_COMMIT() asm volatile("cp.async.commit_group;")
#define CP_WAIT(N)  asm volatile("cp.async.wait_group %0;" :: "n"(N))

__device__ __forceinline__ void mbar_wait(uint32_t mbar, unsigned phase) {
    asm volatile(
        "{\n\t"
        ".reg .pred P;\n\t"
        "LW%=:\n\t"
        "mbarrier.try_wait.parity.acquire.cta.shared::cta.b64 P, [%0], %1, 0x989680;\n\t"
        "@P bra LD%=;\n\t"
        "bra LW%=;\n\t"
        "LD%=:\n\t"
        "}"
        :: "r"(mbar), "r"(phase) : "memory");
}

__device__ __forceinline__ float tanh_fast(float x) {
    float r;
    asm("tanh.approx.f32 %0, %1;" : "=f"(r) : "f"(x));
    return r;
}
__device__ __forceinline__ unsigned h2tanh(unsigned x) {
    unsigned r;
    asm("tanh.approx.f16x2 %0, %1;" : "=r"(r) : "r"(x));
    return r;
}
__device__ __forceinline__ float2 sig_pair_from_halved(float ax, float ay) {
    __half2 h = __floats2half2_rn(ax, ay);
    unsigned u = *reinterpret_cast<unsigned*>(&h);
    u = h2tanh(u);
    __half2 t = *reinterpret_cast<__half2*>(&u);
    float2 tf = __half22float2(t);
    return make_float2(0.5f + 0.5f * tf.x, 0.5f + 0.5f * tf.y);
}

// ---------------- init ----------------
__global__ void k_init() {
    int i = blockIdx.x * blockDim.x + threadIdx.x;
    if (i < T_STEPS) d_bar[i] = 0u;
    unsigned* h = (unsigned*)&d_hh[0][0];
    for (int j = i; j < 2 * 4 * CHALVES / 2; j += gridDim.x * blockDim.x) h[j] = 0u;
}

// ---------------- merged prep: weights (split+scale+fp16) and x (fp16) ----------------
// f,i,o weights pre-scaled by 0.5 so sigmoid(x) = 0.5 + 0.5*tanh(halved preact).
__global__ void k_prep(const float* __restrict__ Wf, const float* __restrict__ Wi,
                       const float* __restrict__ Wc, const float* __restrict__ Wo,
                       const float* __restrict__ X) {
    if (blockIdx.x < WBLKN) {
        size_t idx = (size_t)blockIdx.x * 256 + threadIdx.x;
        int d2  = (int)(idx % (DD / 2));
        int rem = (int)(idx / (DD / 2));
        int j   = rem % HH;
        int g   = rem / HH;
        int d   = 2 * d2;
        const float* W = (g == 0) ? Wf : (g == 1) ? Wi : (g == 2) ? Wc : Wo;
        float sc = (g == 2) ? 1.0f : 0.5f;
        float v0 = W[(size_t)j * DD + d] * sc;
        float v1 = W[(size_t)j * DD + d + 1] * sc;
        __half h0 = __float2half_rn(v0), h1 = __float2half_rn(v1);
        if (d < EE) {
            int n = g * HH + j;
            *(__half2*)(d_Wx16 + (size_t)n * EE + d) = __halves2half2(h0, h1);
        } else {
            int k = d - EE;                 // even
            int bid = j >> 3, jj = j & 7;
            int cstart = bid >> 5;
            int cc = ((k >> 8) - cstart) & 3;
            int k256 = k & 255;
            int sk = k256 >> 6;
            int s  = (k256 >> 4) & 3;
            int kk = k256 & 15;
            int breg = kk >> 3;
            int tg = (kk & 7) >> 1;
            int nh = g >> 1, ntl = g & 1;
            int w = nh * 4 + sk;
            int lane = (jj << 2) | tg;
            int u = cc * 16 + s * 4 + ntl * 2 + breg;
            unsigned pk = ((unsigned)__half_as_ushort(h1) << 16) |
                          (unsigned)__half_as_ushort(h0);   // lo = smaller k
            d_Wh16[(((size_t)bid * 8 + w) * 32 + lane) * 64 + u] = pk;
        }
    } else {
        size_t idx = (size_t)(blockIdx.x - WBLKN) * 256 + threadIdx.x;
        float2 v = ((const float2*)X)[idx];
        ((__half2*)d_X16)[idx] = __halves2half2(__float2half_rn(v.x), __float2half_rn(v.y));
    }
}

// ---------------- x-side GEMM (fp16): Gx[t][b][n] = X @ Wx^T + bias ----------------
__global__ void __launch_bounds__(256) k_gx_gemm(const float* __restrict__ bf, const float* __restrict__ bi,
                                                 const float* __restrict__ bc, const float* __restrict__ bo) {
    __shared__ __half As[2][XBM][XSTR];
    __shared__ __half Bs[2][XBN][XSTR];

    const int tid = threadIdx.x;
    const int warp = tid >> 5, lane = tid & 31;
    const int g8 = lane >> 2, tg = lane & 3;
    const int m0 = blockIdx.y * XBM;
    const int n0 = blockIdx.x * XBN;
    const int wm = (warp & 3) * 32;
    const int wn = (warp >> 2) * 64;

    float acc[2][8][4];
#pragma unroll
    for (int a = 0; a < 2; a++)
#pragma unroll
        for (int b = 0; b < 8; b++)
#pragma unroll
            for (int c = 0; c < 4; c++) acc[a][b][c] = 0.f;

    auto load_chunk = [&](int c, int buf) {
        int k0 = c * XBK;
#pragma unroll
        for (int i = 0; i < 2; i++) {
            int q = tid + i * 256;
            int row = q >> 2, kq = q & 3;
            cpasync16(saddr(&As[buf][row][kq * 8]),
                      d_X16 + (size_t)(m0 + row) * EE + k0 + kq * 8);
            cpasync16(saddr(&Bs[buf][row][kq * 8]),
                      d_Wx16 + (size_t)(n0 + row) * EE + k0 + kq * 8);
        }
    };

    load_chunk(0, 0);
    CP_COMMIT();

    for (int c = 0; c < XKCH; c++) {
        if (c + 1 < XKCH) {
            load_chunk(c + 1, (c + 1) & 1);
            CP_COMMIT();
            CP_WAIT(1);
        } else {
            CP_WAIT(0);
        }
        __syncthreads();
        const int buf = c & 1;
#pragma unroll
        for (int kk = 0; kk < XBK; kk += 16) {
            unsigned a[2][4];
#pragma unroll
            for (int mi = 0; mi < 2; mi++) {
                a[mi][0] = *(const unsigned*)&As[buf][wm + mi * 16 + g8][kk + 2 * tg];
                a[mi][1] = *(const unsigned*)&As[buf][wm + mi * 16 + 8 + g8][kk + 2 * tg];
                a[mi][2] = *(const unsigned*)&As[buf][wm + mi * 16 + g8][kk + 8 + 2 * tg];
                a[mi][3] = *(const unsigned*)&As[buf][wm + mi * 16 + 8 + g8][kk + 8 + 2 * tg];
            }
#pragma unroll
            for (int ni = 0; ni < 8; ni++) {
                unsigned b0 = *(const unsigned*)&Bs[buf][wn + ni * 8 + g8][kk + 2 * tg];
                unsigned b1 = *(const unsigned*)&Bs[buf][wn + ni * 8 + g8][kk + 8 + 2 * tg];
                mma_fp16(acc[0][ni][0], acc[0][ni][1], acc[0][ni][2], acc[0][ni][3],
                         a[0][0], a[0][1], a[0][2], a[0][3], b0, b1);
                mma_fp16(acc[1][ni][0], acc[1][ni][1], acc[1][ni][2], acc[1][ni][3],
                         a[1][0], a[1][1], a[1][2], a[1][3], b0, b1);
            }
        }
        __syncthreads();
    }

#pragma unroll
    for (int mi = 0; mi < 2; mi++) {
        int r0 = m0 + wm + mi * 16 + g8;
        int r1 = r0 + 8;
        size_t o0 = ((size_t)(r0 & (T_STEPS - 1)) * BB + (r0 >> 9)) * NG;
        size_t o1 = ((size_t)(r1 & (T_STEPS - 1)) * BB + (r1 >> 9)) * NG;
#pragma unroll
        for (int ni = 0; ni < 8; ni++) {
            int col = n0 + wn + ni * 8 + 2 * tg;
            int g = col >> 10;
            int jj = col & (HH - 1);
            const float* bp = (g == 0) ? bf : (g == 1) ? bi : (g == 2) ? bc : bo;
            float bsc = (g == 2) ? 1.0f : 0.5f;     // match weight pre-scaling
            float bv0 = bp[jj] * bsc, bv1 = bp[jj + 1] * bsc;
            float2 v0 = make_float2(acc[mi][ni][0] + bv0, acc[mi][ni][1] + bv1);
            float2 v1 = make_float2(acc[mi][ni][2] + bv0, acc[mi][ni][3] + bv1);
            *(float2*)(d_Gx + o0 + col) = v0;
            *(float2*)(d_Gx + o1 + col) = v1;
        }
    }
}

// ---------------- persistent recurrent kernel (warp-specialized) ----------------
// 128 blocks x 288 threads. Warps 0-7 compute, warp 8 produces.
// h in gmem is chunk-major with a per-row XOR-16B-unit swizzle; each chunk is one
// contiguous 32KB cp.async.bulk (4 requests/step total).
__global__ void __launch_bounds__(288, 1) k_lstm_rec() {
    extern __shared__ char smemc[];
    __half*   hs   = (__half*)smemc;                             // [4][64][256] (swizzled rows)
    float*    Csm  = (float*)(smemc + 4 * CBYTES);               // [4 sk][64 m][34]
    uint64_t* mbar = (uint64_t*)(smemc + 4 * CBYTES + 4 * 64 * 34 * 4);

    const int tid  = threadIdx.x;
    const int bid  = blockIdx.x;
    const int w    = tid >> 5, lane = tid & 31;
    const int g8   = lane >> 2, tg = lane & 3;
    const int j0   = bid * JPB;
    const int cstart = bid >> 5;

    const uint32_t mbbase = saddr(&mbar[0]);
    const uint32_t hsb    = saddr(hs);

    if (tid == 0) {
#pragma unroll
        for (int i = 0; i < 4; i++)
            asm volatile("mbarrier.init.shared::cta.b64 [%0], 1;" :: "r"(mbbase + i * 8));
        asm volatile("fence.proxy.async.shared::cta;" ::: "memory");
    }
    __syncthreads();

    if (w == 8) {
        // ---------------- producer warp ----------------
        for (int t = 0; t < T_STEPS; t++) {
            const __half* hsrc = &d_hh[t & 1][0];
            if (t > 0) {
                if (lane == 0) {
                    const unsigned* p = &d_bar[t - 1];
                    unsigned v;
                    while (true) {
                        asm volatile("ld.acquire.gpu.global.u32 %0, [%1];"
                                     : "=r"(v) : "l"(p) : "memory");
                        if (v >= (unsigned)GBLK) break;
                        __nanosleep(64);
                    }
                }
                __syncwarp();
                asm volatile("fence.proxy.async;" ::: "memory");
            }
            if (lane < 4) {
                const int cc = lane;
                const int ca = (cc + cstart) & 3;
                const uint32_t fmb = mbbase + cc * 8;
                asm volatile("mbarrier.arrive.expect_tx.shared::cta.b64 _, [%0], %1;"
                             :: "r"(fmb), "r"(CBYTES) : "memory");
                const __half* src = hsrc + (size_t)ca * CHALVES;
                asm volatile(
                    "cp.async.bulk.shared::cta.global.mbarrier::complete_tx::bytes [%0], [%1], %2, [%3];"
                    :: "r"(hsb + cc * CBYTES), "l"(src), "r"(CBYTES), "r"(fmb) : "memory");
            }
        }
        return;
    }

    // ---------------- compute warps (0-7) ----------------
    const int nh = w >> 2, sk = w & 3;

    unsigned wreg[64];
    {
        const uint4* wp = (const uint4*)(d_Wh16 + (((size_t)bid * 8 + w) * 32 + lane) * 64);
#pragma unroll
        for (int i = 0; i < 16; i++) *(uint4*)&wreg[i * 4] = wp[i];
    }

    const int eb  = tid >> 2;
    const int ej2 = tid & 3;
    float2 cst = make_float2(0.f, 0.f);

    for (int t = 0; t < T_STEPS; t++) {
        const float* gx = d_Gx + (size_t)t * BB * NG + (size_t)eb * NG + j0 + 2 * ej2;
        float2 gxv[4];
#pragma unroll
        for (int g = 0; g < 4; g++) gxv[g] = __ldg((const float2*)(gx + g * HH));

        float acc[2][4][4];
#pragma unroll
        for (int a = 0; a < 2; a++)
#pragma unroll
            for (int b = 0; b < 4; b++)
#pragma unroll
                for (int c = 0; c < 4; c++) acc[a][b][c] = 0.f;

#pragma unroll 1
        for (int cc = 0; cc < 4; cc++) {
            mbar_wait(mbbase + cc * 8, t & 1);
            const char* hbB = (const char*)hs + cc * CBYTES + 4 * tg;
#pragma unroll
            for (int s = 0; s < 4; s++) {
                const int u0 = (sk * 8 + 2 * s) ^ g8;   // swizzled 16B unit
                const int u1 = u0 ^ 1;
#pragma unroll
                for (int mt = 0; mt < 4; mt++) {
                    const char* p0 = hbB + (mt * 16 + g8) * 512;
                    unsigned a0 = *(const unsigned*)(p0 + u0 * 16);
                    unsigned a1 = *(const unsigned*)(p0 + 8 * 512 + u0 * 16);
                    unsigned a2 = *(const unsigned*)(p0 + u1 * 16);
                    unsigned a3 = *(const unsigned*)(p0 + 8 * 512 + u1 * 16);
#pragma unroll
                    for (int ntl = 0; ntl < 2; ntl++) {
                        const int u = cc * 16 + s * 4 + ntl * 2;
                        mma_fp16(acc[ntl][mt][0], acc[ntl][mt][1], acc[ntl][mt][2], acc[ntl][mt][3],
                                 a0, a1, a2, a3, wreg[u], wreg[u + 1]);
                    }
                }
            }
        }

        // stage partials: Csm[sk][m][n(32) padded to 34]
#pragma unroll
        for (int ntl = 0; ntl < 2; ntl++) {
            const int nb = nh * 16 + ntl * 8 + 2 * tg;
#pragma unroll
            for (int mt = 0; mt < 4; mt++) {
                float* cp = Csm + (size_t)(sk * 64 + mt * 16 + g8) * 34 + nb;
                *(float2*)cp              = make_float2(acc[ntl][mt][0], acc[ntl][mt][1]);
                *(float2*)(cp + 8 * 34)   = make_float2(acc[ntl][mt][2], acc[ntl][mt][3]);
            }
        }
        asm volatile("bar.sync 1, 256;" ::: "memory");

        // epilogue: reduce 4 k-slices, gates, update c, write swizzled fp16 h
        {
            float2 a4[4];
#pragma unroll
            for (int g = 0; g < 4; g++) {
                float2 s = gxv[g];
#pragma unroll
                for (int q = 0; q < 4; q++) {
                    float2 v = *(const float2*)(Csm + (size_t)(q * 64 + eb) * 34 + g * 8 + 2 * ej2);
                    s.x += v.x; s.y += v.y;
                }
                a4[g] = s;
            }
            float2 fg = sig_pair_from_halved(a4[0].x, a4[0].y);
            float2 ig = sig_pair_from_halved(a4[1].x, a4[1].y);
            float2 og = sig_pair_from_halved(a4[3].x, a4[3].y);
            float cgx = tanh_fast(a4[2].x), cgy = tanh_fast(a4[2].y);
            cst.x = __fmaf_rn(fg.x, cst.x, ig.x * cgx);
            cst.y = __fmaf_rn(fg.y, cst.y, ig.y * cgy);
            float hnx = og.x * tanh_fast(cst.x);
            float hny = og.y * tanh_fast(cst.y);
            const int swu = (bid & 31) ^ (eb & 7);   // swizzled 16B unit within row
            __half2* hd = (__half2*)(&d_hh[(t + 1) & 1][0] +
                                     (size_t)cstart * CHALVES + eb * 256 + swu * 8 + 2 * ej2);
            *hd = __halves2half2(__float2half_rn(hnx), __float2half_rn(hny));
            if (t == T_STEPS - 1)
                *(float2*)(d_hfin + (size_t)eb * HH + j0 + 2 * ej2) = make_float2(hnx, hny);
        }

        asm volatile("bar.sync 1, 256;" ::: "memory");
        if (tid == 0 && t < T_STEPS - 1)
            asm volatile("red.release.gpu.global.add.u32 [%0], %1;"
                         :: "l"(&d_bar[t]), "r"(1u) : "memory");
    }
}

// ---------------- final FC (exact fp32) ----------------
__global__ void k_fc(const float* __restrict__ Wfc, const float* __restrict__ bfc,
                     float* __restrict__ out) {
    int b = blockIdx.x, n = blockIdx.y;
    const float* h = d_hfin + (size_t)b * HH;
    const float* w = Wfc + (size_t)n * HH;
    float s = 0.f;
    for (int k = threadIdx.x; k < HH; k += 128) s += h[k] * w[k];
#pragma unroll
    for (int o = 16; o > 0; o >>= 1) s += __shfl_down_sync(0xFFFFFFFFu, s, o);
    __shared__ float red[4];
    if ((threadIdx.x & 31) == 0) red[threadIdx.x >> 5] = s;
    __syncthreads();
    if (threadIdx.x == 0)
        out[b * NCLS + n] = red[0] + red[1] + red[2] + red[3] + bfc[n];
}

// ---------------- launch ----------------
extern "C" void kernel_launch(void* const* d_in, const int* in_sizes, int n_in,
                              void* d_out, int out_size) {
    const float* X   = (const float*)d_in[0];
    const float* Wf  = (const float*)d_in[1];
    const float* bf  = (const float*)d_in[2];
    const float* Wi  = (const float*)d_in[3];
    const float* bi  = (const float*)d_in[4];
    const float* Wc  = (const float*)d_in[5];
    const float* bc  = (const float*)d_in[6];
    const float* Wo  = (const float*)d_in[7];
    const float* bo  = (const float*)d_in[8];
    const float* Wfc = (const float*)d_in[9];
    const float* bfc = (const float*)d_in[10];

    const int rec_smem = 4 * CBYTES + 4 * 64 * 34 * 4 + 64;  // 131072 + 34816 + 64
    cudaFuncSetAttribute(k_lstm_rec, cudaFuncAttributeMaxDynamicSharedMemorySize, rec_smem);

    k_init<<<64, 256>>>();
    k_prep<<<WBLKN + XBLKN, 256>>>(Wf, Wi, Wc, Wo, X);
    k_gx_gemm<<<dim3(NG / XBN, (BB * T_STEPS) / XBM), 256>>>(bf, bi, bc, bo);
    k_lstm_rec<<<GBLK, 288, rec_smem>>>();
    k_fc<<<dim3(BB, NCLS), 128>>>(Wfc, bfc, (float*)d_out);
}